// round 16
// baseline (speedup 1.0000x reference)
#include <cuda_runtime.h>
#include <cuda_fp16.h>
#include <cstdint>

#define NB   8192
#define ND   1024
#define NE   32
#define NA   128
#define NBNA (NB * NA)

#define UZ    8                   // expert splits (partial slots)
#define EPC   (NE / UZ)           // 4 experts per unit
#define NITU  (EPC * 16)          // 64 iterations per unit
#define UM    64                  // M tiles
#define UNITS (UM * UZ)           // 512
#define GRID_STRAT 296            // 2 CTAs/SM x 148 SMs

// ---------------- device-global scratch (no allocs) ----------------
__device__ float  g_weights[NB * NE];
__device__ float  g_wb[NBNA];             // weighted bias plane
__device__ float  g_part[UZ * NBNA];
__device__ __half g_xh[NB * ND];          // fp16, k16-interleaved
__device__ __half g_wh[NE * NA * ND];
__device__ int    g_ctr;                  // work-steal counter
__device__ int    g_done[UM];             // per-m-tile completion counters

// ---------------- helpers ----------------
__device__ __forceinline__ uint32_t smem_u32(const void* p) {
    uint32_t a;
    asm("{ .reg .u64 t; cvta.to.shared.u64 t, %1; cvt.u32.u64 %0, t; }" : "=r"(a) : "l"(p));
    return a;
}
__device__ __forceinline__ void cp16(uint32_t dst, const void* src) {
    asm volatile("cp.async.cg.shared.global [%0], [%1], 16;" :: "r"(dst), "l"(src) : "memory");
}
#define CP_COMMIT() asm volatile("cp.async.commit_group;" ::: "memory")
template <int N> __device__ __forceinline__ void cp_wait() {
    asm volatile("cp.async.wait_group %0;" :: "n"(N) : "memory");
}
__device__ __forceinline__ void mma16f(float* d, uint32_t a0, uint32_t a1,
                                       uint32_t a2, uint32_t a3,
                                       uint32_t b0, uint32_t b1) {
    asm volatile("mma.sync.aligned.m16n8k16.row.col.f32.f16.f16.f32 "
                 "{%0,%1,%2,%3}, {%4,%5,%6,%7}, {%8,%9}, {%0,%1,%2,%3};"
                 : "+f"(d[0]), "+f"(d[1]), "+f"(d[2]), "+f"(d[3])
                 : "r"(a0), "r"(a1), "r"(a2), "r"(a3), "r"(b0), "r"(b1));
}
__device__ __forceinline__ uint32_t hmul2u(uint32_t a, uint32_t w) {
    __half2 r = __hmul2(*(__half2*)&a, *(__half2*)&w);
    return *(uint32_t*)&r;
}

// smem (bytes): BK=64 halves, row stride 160 B, 2 stages
#define TSTRB  160
#define TILEB  (128 * TSTRB)
#define STAGEB (2 * TILEB)               // 40960
#define WSMO   (2 * STAGEB)              // 81920
#define SMEM_STRAT (WSMO + EPC * 128 * 4)    // 83968 B -> 2 CTAs/SM

// ============================================================================
// Kernel 0: W_strat fp32 -> fp16 + k16-interleave; resets counters.
// ============================================================================
__global__ void __launch_bounds__(256)
round_w_kernel(const float* __restrict__ src, __half* __restrict__ dst, int n16) {
    if (blockIdx.x == 0) {
        if (threadIdx.x == 0) g_ctr = 0;
        if (threadIdx.x < UM) g_done[threadIdx.x] = 0;
    }
    int i = blockIdx.x * blockDim.x + threadIdx.x;
    if (i < n16) {
        const float4* s = (const float4*)src + 4 * (size_t)i;
        float4 v0 = s[0], v1 = s[1], v2 = s[2], v3 = s[3];
        __half2 h[8];
        h[0] = __floats2half2_rn(v0.x, v0.y);   // k0,k1
        h[1] = __floats2half2_rn(v2.x, v2.y);   // k8,k9
        h[2] = __floats2half2_rn(v0.z, v0.w);   // k2,k3
        h[3] = __floats2half2_rn(v2.z, v2.w);   // k10,k11
        h[4] = __floats2half2_rn(v1.x, v1.y);   // k4,k5
        h[5] = __floats2half2_rn(v3.x, v3.y);   // k12,k13
        h[6] = __floats2half2_rn(v1.z, v1.w);   // k6,k7
        h[7] = __floats2half2_rn(v3.z, v3.w);   // k14,k15
        uint4* d = (uint4*)(dst + 16 * (size_t)i);
        d[0] = *(uint4*)&h[0];
        d[1] = *(uint4*)&h[4];
    }
}

// ============================================================================
// Kernel 1: gating + fused x fp16 emit + weighted-bias plane wb[b,a].
// ============================================================================
__global__ void __launch_bounds__(256)
gate_kernel(const float* __restrict__ x,  const float* __restrict__ Watt,
            const float* __restrict__ batt, const float* __restrict__ abias,
            const float* __restrict__ gum,  const float* __restrict__ bstrat,
            __half* __restrict__ xh) {
    __shared__ float Wsm[NE * 64];           // 8 KB
    __shared__ float red[8 * 33 * 32];       // 33.8 KB; reused for bias staging

    const int tid  = threadIdx.x;
    const int lane = tid & 31;
    const int wid  = tid >> 5;
    const int r0   = blockIdx.x * 16 + wid * 2;
    const int r1   = r0 + 1;

    const int grp  = lane >> 3;
    const int j    = lane & 7;
    const int slot = (j < 4) ? (2 * j) : (2 * (j - 4) + 1);

    float la[NE], lb[NE];
#pragma unroll
    for (int e = 0; e < NE; ++e) { la[e] = 0.f; lb[e] = 0.f; }

    for (int kt = 0; kt < 16; ++kt) {
        __syncthreads();
#pragma unroll
        for (int p = 0; p < 4; ++p) {
            int idx = tid + 256 * p;
            int e = idx >> 5, k2 = idx & 31;
            *(float2*)&Wsm[e * 64 + k2 * 2] =
                *(const float2*)&Watt[(size_t)e * ND + kt * 64 + k2 * 2];
        }
        __syncthreads();
        float2 xa = *(const float2*)&x[(size_t)r0 * ND + kt * 64 + lane * 2];
        float2 xb = *(const float2*)&x[(size_t)r1 * ND + kt * 64 + lane * 2];

        {   // fused fp16 emit (k16-interleaved)
            size_t off = (size_t)(kt * 4 + grp) * 16 + slot * 2;
            *(__half2*)(xh + (size_t)r0 * ND + off) = __floats2half2_rn(xa.x, xa.y);
            *(__half2*)(xh + (size_t)r1 * ND + off) = __floats2half2_rn(xb.x, xb.y);
        }

#pragma unroll
        for (int e = 0; e < NE; ++e) {
            float2 wv = *(const float2*)&Wsm[e * 64 + lane * 2];
            la[e] = fmaf(xa.x, wv.x, fmaf(xa.y, wv.y, la[e]));
            lb[e] = fmaf(xb.x, wv.x, fmaf(xb.y, wv.y, lb[e]));
        }
    }

    float wrow[2];
    float* pr = &red[wid * 33 * 32];
#pragma unroll
    for (int half = 0; half < 2; ++half) {
        float* src = half ? lb : la;
        int row = half ? r1 : r0;
#pragma unroll
        for (int e = 0; e < NE; ++e) pr[lane * 33 + e] = src[e];
        __syncwarp();
        float logit = 0.f;
#pragma unroll
        for (int l = 0; l < 32; ++l) logit += pr[l * 33 + lane];
        logit += batt[lane] + abias[lane];
        float u = gum[row * NE + lane];
        logit += -logf(-logf(u + 1e-10f) + 1e-10f);
        float mx = logit;
#pragma unroll
        for (int o = 16; o > 0; o >>= 1) mx = fmaxf(mx, __shfl_xor_sync(0xffffffffu, mx, o));
        float p = expf(logit - mx);
        float s = p;
#pragma unroll
        for (int o = 16; o > 0; o >>= 1) s += __shfl_xor_sync(0xffffffffu, s, o);
        float w = p / s;
        g_weights[row * NE + lane] = w;
        wrow[half] = w;
        __syncwarp();
    }

    // ---- weighted bias: wb[row][a] = sum_e w[row][e] * bstrat[e][a] ----
    __syncthreads();                         // red no longer needed for transpose
    float* bs_sm = red;                      // 32 x 128 floats staged
#pragma unroll
    for (int p = 0; p < 4; ++p) {
        int idx = tid + 256 * p;
        ((float4*)bs_sm)[idx] = ((const float4*)bstrat)[idx];
    }
    __syncthreads();
#pragma unroll
    for (int half = 0; half < 2; ++half) {
        const int row = half ? r1 : r0;
        const float w = wrow[half];
        float wb4[4] = {0.f, 0.f, 0.f, 0.f};
#pragma unroll
        for (int e = 0; e < NE; ++e) {
            float we = __shfl_sync(0xffffffffu, w, e);
#pragma unroll
            for (int q = 0; q < 4; ++q)
                wb4[q] = fmaf(we, bs_sm[e * 128 + lane + q * 32], wb4[q]);
        }
#pragma unroll
        for (int q = 0; q < 4; ++q)
            g_wb[(size_t)row * NA + lane + q * 32] = wb4[q];
    }
}

// ============================================================================
// Kernel 2: persistent fused GEMM + last-CTA-per-m-tile final reduction.
// ============================================================================
__device__ __forceinline__ void load_xw64h(const __half* __restrict__ xh,
                                           const __half* __restrict__ wh,
                                           int m0, int eidx, int kt,
                                           uint32_t xs, uint32_t ws, int tid) {
    const __half* xsrc = xh + (size_t)m0 * ND + kt * 64;
    const __half* wsrc = wh + (size_t)eidx * NA * ND + kt * 64;
#pragma unroll
    for (int p = 0; p < 4; ++p) {
        int idx = tid + 256 * p;
        int r = idx >> 3, c = idx & 7;
        cp16(xs + r * TSTRB + c * 16, xsrc + (size_t)r * ND + c * 8);
    }
#pragma unroll
    for (int p = 0; p < 4; ++p) {
        int idx = tid + 256 * p;
        int r = idx >> 3, c = idx & 7;
        cp16(ws + r * TSTRB + c * 16, wsrc + (size_t)r * ND + c * 8);
    }
}

__global__ void __launch_bounds__(256, 2)
strat_mma_kernel(const __half* __restrict__ xh, const __half* __restrict__ wh,
                 float* __restrict__ out) {
    extern __shared__ char dynsm[];
    __shared__ int s_u;
    __shared__ int s_last;
    const uint32_t smb = smem_u32(dynsm);
    const int tid    = threadIdx.x;
    const int lane   = tid & 31;
    const int wid    = tid >> 5;
    const int warp_m = wid & 1;
    const int warp_n = wid >> 1;
    const int g      = lane >> 2;
    const int c      = lane & 3;

    uint32_t* w_sm = (uint32_t*)(dynsm + WSMO);   // duplicated half2 [e][m]

    for (;;) {
        if (tid == 0) s_u = atomicAdd(&g_ctr, 1);
        __syncthreads();
        const int u = s_u;
        if (u >= UNITS) break;

        const int mt    = u & (UM - 1);
        const int m0    = mt << 7;
        const int zz    = u >> 6;
        const int ebase = zz * EPC;

        // gating weights (duplicated half2): e = idx>>7, m = idx&127
#pragma unroll
        for (int p = 0; p < EPC * 128 / 256; ++p) {
            int idx = tid + 256 * p;
            float w = g_weights[(size_t)(m0 + (idx & 127)) * NE + ebase + (idx >> 7)];
            __half2 h = __float2half2_rn(w);
            w_sm[idx] = *(uint32_t*)&h;
        }

        float acc[4][4][4];
#pragma unroll
        for (int tm = 0; tm < 4; ++tm)
#pragma unroll
            for (int tn = 0; tn < 4; ++tn)
#pragma unroll
                for (int q = 0; q < 4; ++q) acc[tm][tn][q] = 0.f;

        load_xw64h(xh, wh, m0, ebase, 0, smb, smb + TILEB, tid);
        CP_COMMIT();

        int s = 0;
        for (int it = 0; it < NITU; ++it) {
            cp_wait<0>();
            __syncthreads();

            if (it + 1 < NITU) {
                const int ni = it + 1;
                load_xw64h(xh, wh, m0, ebase + (ni >> 4), ni & 15,
                           smb + (s ^ 1) * STAGEB, smb + (s ^ 1) * STAGEB + TILEB, tid);
            }
            CP_COMMIT();

            const char* xsf = dynsm + s * STAGEB;
            const char* wsf = xsf + TILEB;
            const int e = it >> 4;

            uint32_t wl2[4], wh2[4];
#pragma unroll
            for (int tm = 0; tm < 4; ++tm) {
                const int row = warp_m * 64 + tm * 16 + g;
                wl2[tm] = w_sm[e * 128 + row];
                wh2[tm] = w_sm[e * 128 + row + 8];
            }

#pragma unroll
            for (int ks = 0; ks < 4; ++ks) {
                const int ko = ks * 32 + c * 8;
                uint2 alo[4], ahi[4], bu[4];
#pragma unroll
                for (int tm = 0; tm < 4; ++tm) {
                    const int row = warp_m * 64 + tm * 16 + g;
                    alo[tm] = *(const uint2*)(xsf + row * TSTRB + ko);
                    ahi[tm] = *(const uint2*)(xsf + (row + 8) * TSTRB + ko);
                }
#pragma unroll
                for (int tn = 0; tn < 4; ++tn) {
                    const int row = warp_n * 32 + tn * 8 + g;
                    bu[tn] = *(const uint2*)(wsf + row * TSTRB + ko);
                }
#pragma unroll
                for (int tm = 0; tm < 4; ++tm) {
                    alo[tm].x = hmul2u(alo[tm].x, wl2[tm]);
                    alo[tm].y = hmul2u(alo[tm].y, wl2[tm]);
                    ahi[tm].x = hmul2u(ahi[tm].x, wh2[tm]);
                    ahi[tm].y = hmul2u(ahi[tm].y, wh2[tm]);
                }
#pragma unroll
                for (int tm = 0; tm < 4; ++tm)
#pragma unroll
                    for (int tn = 0; tn < 4; ++tn)
                        mma16f(acc[tm][tn], alo[tm].x, ahi[tm].x, alo[tm].y, ahi[tm].y,
                               bu[tn].x, bu[tn].y);
            }

            s ^= 1;
        }

        // write partial -> g_part[zz]
        float* dst = g_part + (size_t)zz * NBNA;
#pragma unroll
        for (int tm = 0; tm < 4; ++tm) {
            const int row = m0 + warp_m * 64 + tm * 16 + g;
#pragma unroll
            for (int tn = 0; tn < 4; ++tn) {
                const int col = warp_n * 32 + tn * 8 + 2 * c;
                *(float2*)&dst[(size_t)row * NA + col] =
                    make_float2(acc[tm][tn][0], acc[tm][tn][1]);
                *(float2*)&dst[(size_t)(row + 8) * NA + col] =
                    make_float2(acc[tm][tn][2], acc[tm][tn][3]);
            }
        }

        // completion handshake: last arriver reduces the m-tile
        __threadfence();
        __syncthreads();
        if (tid == 0) s_last = (atomicAdd(&g_done[mt], 1) == UZ - 1) ? 1 : 0;
        __syncthreads();
        if (s_last) {
            __threadfence();   // acquire side: partials from other CTAs visible
            const size_t base = (size_t)m0 * NA;
#pragma unroll
            for (int p = 0; p < 16; ++p) {
                const size_t idx = base + p * 1024 + tid * 4;
                float4 a = *(const float4*)&g_wb[idx];
#pragma unroll
                for (int z = 0; z < UZ; ++z) {
                    float4 pv = *(const float4*)&g_part[(size_t)z * NBNA + idx];
                    a.x += pv.x; a.y += pv.y; a.z += pv.z; a.w += pv.w;
                }
                *(float4*)&out[idx] = a;
            }
        }
    }
}

// ============================================================================
extern "C" void kernel_launch(void* const* d_in, const int* in_sizes, int n_in,
                              void* d_out, int out_size) {
    const float* x      = (const float*)d_in[0];
    const float* Watt   = (const float*)d_in[1];
    const float* batt   = (const float*)d_in[2];
    const float* abias  = (const float*)d_in[3];
    const float* Wstrat = (const float*)d_in[4];
    const float* bstrat = (const float*)d_in[5];
    const float* gum    = (const float*)d_in[6];
    float* out          = (float*)d_out;

    __half* xh = nullptr; __half* wh = nullptr;
    cudaGetSymbolAddress((void**)&xh, g_xh);
    cudaGetSymbolAddress((void**)&wh, g_wh);

    round_w_kernel<<<(NE * NA * ND / 16 + 255) / 256, 256>>>(Wstrat, wh, NE * NA * ND / 16);
    gate_kernel<<<NB / 16, 256>>>(x, Watt, batt, abias, gum, bstrat, xh);

    cudaFuncSetAttribute(strat_mma_kernel,
                         cudaFuncAttributeMaxDynamicSharedMemorySize, SMEM_STRAT);
    strat_mma_kernel<<<GRID_STRAT, 256, SMEM_STRAT>>>(xh, wh, out);
}